// round 10
// baseline (speedup 1.0000x reference)
#include <cuda_runtime.h>
#include <cuda_bf16.h>
#include <math.h>
#include <stdint.h>

#define BS 32
#define NN 256
#define EE 64
#define CC 512
#define HH 4
#define LL 2
#define MM 65

typedef __nv_bfloat16 bf16;

// ---------------- fp32 scratch ----------------
__device__ float g_ohp[(size_t)BS*HH*NN*CC];
__device__ float g_agg[(size_t)2*BS*NN*CC];
__device__ float g_xroot[(size_t)BS*NN*CC];
__device__ float g_xr[(size_t)BS*NN*CC];
__device__ float g_xh[(size_t)BS*NN*CC];
__device__ float g_ae[BS*MM*HH];
__device__ float g_vx[HH*CC];
__device__ float g_ve[HH*CC];
__device__ float g_invD[BS*NN];
__device__ float g_invB[BS*MM];
__device__ float g_amn0f[BS*HH*NN];   // alpha(m=0), unscaled
__device__ float g_anm0f[BS*HH*NN];   // alpha(m=0) * invB[0]
__device__ float g_t0[BS*HH*CC];      // t row m=0 (fp32)
__device__ float g_msg0[BS*HH*CC];    // msg row m=0 (fp32)
__device__ float g_ctx[BS*2*CC];
__device__ float g_h1[BS*2*CC];
__device__ float g_ctx2[BS*2*CC];

// ---------------- bf16 hi/lo planes ----------------
__device__ bf16 g_x0h[(size_t)BS*NN*CC],      g_x0l[(size_t)BS*NN*CC];
__device__ bf16 g_wlh[(size_t)LL*CC*HH*CC],   g_wll[(size_t)LL*CC*HH*CC];
__device__ bf16 g_wrh[(size_t)LL*2*CC*CC],    g_wrl[(size_t)LL*2*CC*CC];
__device__ bf16 g_wth[(size_t)LL*CC*CC],      g_wtl[(size_t)LL*CC*CC];
__device__ bf16 g_amnh[(size_t)BS*HH*MM*NN],  g_amnl[(size_t)BS*HH*MM*NN];
__device__ bf16 g_anmh[(size_t)BS*HH*NN*EE],  g_anml[(size_t)BS*HH*NN*EE];
__device__ bf16 g_th[(size_t)BS*HH*MM*CC],    g_tl[(size_t)BS*HH*MM*CC];
__device__ bf16 g_msgh[(size_t)BS*HH*MM*CC],  g_msgl[(size_t)BS*HH*MM*CC];
__device__ bf16 g_xwh[(size_t)2*BS*NN*CC],    g_xwl[(size_t)2*BS*NN*CC];
__device__ bf16 g_Anh[(size_t)2*BS*NN*NN],    g_Anl[(size_t)2*BS*NN*NN];
__device__ bf16 g_xrh[(size_t)BS*NN*CC],      g_xrl[(size_t)BS*NN*CC];
__device__ bf16 g_xhh[(size_t)BS*NN*CC],      g_xhl[(size_t)BS*NN*CC];

// ---------------- helpers ----------------
__device__ __forceinline__ void split_bf(float x, bf16& h, bf16& l) {
    h = __float2bfloat16(x);
    l = __float2bfloat16(x - __bfloat162float(h));
}
__device__ __forceinline__ uint32_t pack_split_hi(float a, float b, uint32_t& lo_out) {
    bf16 h0, l0, h1, l1;
    split_bf(a, h0, l0); split_bf(b, h1, l1);
    __nv_bfloat162 hp; hp.x = h0; hp.y = h1;
    __nv_bfloat162 lp; lp.x = l0; lp.y = l1;
    uint32_t hv, lv;
    __builtin_memcpy(&hv, &hp, 4); __builtin_memcpy(&lv, &lp, 4);
    lo_out = lv; return hv;
}
__device__ __forceinline__ void mma_bf16(float* c, const uint32_t* a, const uint32_t* b) {
    asm volatile(
        "mma.sync.aligned.m16n8k16.row.col.f32.bf16.bf16.f32 "
        "{%0,%1,%2,%3}, {%4,%5,%6,%7}, {%8,%9}, {%0,%1,%2,%3};\n"
        : "+f"(c[0]), "+f"(c[1]), "+f"(c[2]), "+f"(c[3])
        : "r"(a[0]), "r"(a[1]), "r"(a[2]), "r"(a[3]), "r"(b[0]), "r"(b[1]));
}
__device__ __forceinline__ void cp16(uint32_t dst, const void* src, int sz) {
    asm volatile("cp.async.cg.shared.global [%0], [%1], 16, %2;\n"
                 :: "r"(dst), "l"(src), "r"(sz));
}
#define LDSM4(d0,d1,d2,d3,a) \
    asm volatile("ldmatrix.sync.aligned.m8n8.x4.shared.b16 {%0,%1,%2,%3}, [%4];" \
                 : "=r"(d0),"=r"(d1),"=r"(d2),"=r"(d3) : "r"(a))
#define LDSM4T(d0,d1,d2,d3,a) \
    asm volatile("ldmatrix.sync.aligned.m8n8.x4.trans.shared.b16 {%0,%1,%2,%3}, [%4];" \
                 : "=r"(d0),"=r"(d1),"=r"(d2),"=r"(d3) : "r"(a))

// ================= mma.sync split-bf16 GEMM, tile TMx128x32 =================
// C = (Ah+Al)@(Bh+Bl) via AhBh + AhBl + AlBh, fp32 accum. 256 threads, 8 warps
// (2 x 4), warp tile (TM/2)x32. Double-buffered cp.async + ldmatrix + swizzle.
template<int TM>
__global__ __launch_bounds__(256, 2)
void gemm_kernel(const bf16* __restrict__ Ah, const bf16* __restrict__ Al,
                 const bf16* __restrict__ Bh, const bf16* __restrict__ Bl,
                 float* __restrict__ Cf, bf16* __restrict__ Chp, bf16* __restrict__ Clp,
                 int Mr, int Nc, int K, int lda, int ldb, int ldc,
                 int zdiv,
                 long long sA1, long long sA2,
                 long long sB1, long long sB2,
                 long long sC1, long long sC2)
{
    constexpr int ABYTES = TM * 64;           // per A plane per stage
    constexpr int STG = 2 * ABYTES + 16384;   // Ah | Al | Bh(8K) | Bl(8K)
    constexpr int AN = TM / 64;               // A cp16 chunks per thread per plane
    constexpr int MT = TM / 32;               // m-tiles per warp

    extern __shared__ __align__(128) unsigned char smem_raw[];
    uint32_t smem = (uint32_t)__cvta_generic_to_shared(smem_raw);

    int z = blockIdx.z;
    int z1 = z / zdiv, z2 = z % zdiv;
    long long offA = z1 * sA1 + z2 * sA2;
    long long offB = z1 * sB1 + z2 * sB2;
    long long offC = z1 * sC1 + z2 * sC2;
    Ah += offA; Al += offA; Bh += offB; Bl += offB;

    const int tid = threadIdx.x;
    const int warp = tid >> 5, lane = tid & 31;
    const int wm = warp >> 2, wn = warp & 3;
    const int g = lane >> 2, tg = lane & 3;
    const int rowBase = blockIdx.y * TM;
    const int colBase = blockIdx.x * 128;

    int am[AN], ac[AN], adst[AN];
    int bk[2], bc[2], bdst[2];
    #pragma unroll
    for (int i = 0; i < AN; i++) {
        int q = i * 256 + tid;
        am[i] = q >> 2; ac[i] = q & 3;
        adst[i] = am[i] * 64 + ((ac[i] ^ (am[i] & 3)) << 4);
    }
    #pragma unroll
    for (int i = 0; i < 2; i++) {
        int q = i * 256 + tid;
        bk[i] = q >> 4; bc[i] = q & 15;
        bdst[i] = bk[i] * 256 + ((bc[i] ^ (bk[i] & 7)) << 4);
    }

    int mloc = wm * (TM / 2) + (lane & 15);
    int addrA0 = mloc * 64 + (((lane >> 4) ^ (mloc & 3)) << 4);
    int kB = lane & 15;
    int cB0 = wn * 4 + (lane >> 4);
    int addrB0 = kB * 256 + ((cB0 ^ (kB & 7)) << 4);

    float acc[MT][4][4];
    #pragma unroll
    for (int i = 0; i < MT; i++)
        #pragma unroll
        for (int j = 0; j < 4; j++)
            #pragma unroll
            for (int r = 0; r < 4; r++) acc[i][j][r] = 0.f;

    const int S = (K + 31) / 32;

    auto copy_stage = [&](int s, int buf) {
        int k0 = s * 32;
        uint32_t base = smem + buf * STG;
        #pragma unroll
        for (int i = 0; i < AN; i++) {
            int gr = rowBase + am[i];
            int kk = k0 + ac[i] * 8;
            int rem = (gr < Mr) ? (K - kk) * 2 : 0;
            int sz = rem < 0 ? 0 : (rem > 16 ? 16 : rem);
            int grc = (gr < Mr) ? gr : 0;
            int kkc = (sz > 0) ? kk : 0;
            size_t so = (size_t)grc * lda + kkc;
            cp16(base + adst[i],          Ah + so, sz);
            cp16(base + ABYTES + adst[i], Al + so, sz);
        }
        #pragma unroll
        for (int i = 0; i < 2; i++) {
            int kk = k0 + bk[i];
            int gc = colBase + bc[i] * 8;
            int ok = (kk < K) && (gc < Nc);
            int kkc = ok ? kk : 0;
            int gcc = ok ? gc : 0;
            size_t so = (size_t)kkc * ldb + gcc;
            cp16(base + 2 * ABYTES + bdst[i],        Bh + so, ok ? 16 : 0);
            cp16(base + 2 * ABYTES + 8192 + bdst[i], Bl + so, ok ? 16 : 0);
        }
    };

    copy_stage(0, 0);
    asm volatile("cp.async.commit_group;\n");

    for (int s = 0; s < S; s++) {
        if (s + 1 < S) copy_stage(s + 1, (s + 1) & 1);
        asm volatile("cp.async.commit_group;\n");
        asm volatile("cp.async.wait_group 1;\n");
        __syncthreads();

        uint32_t aH = smem + (s & 1) * STG;
        uint32_t aL = aH + ABYTES;
        uint32_t bH = aH + 2 * ABYTES;
        uint32_t bL = bH + 8192;

        #pragma unroll
        for (int ks = 0; ks < 2; ks++) {
            int axor = ks * 32;
            int bofs = ks * 4096;
            uint32_t Afh[MT][4], Bfh[4][2];
            #pragma unroll
            for (int mt = 0; mt < MT; mt++)
                LDSM4(Afh[mt][0], Afh[mt][1], Afh[mt][2], Afh[mt][3],
                      aH + (uint32_t)(((addrA0 + mt * 1024) ^ axor)));
            #pragma unroll
            for (int u = 0; u < 2; u++) {
                uint32_t d0, d1, d2, d3;
                LDSM4T(d0, d1, d2, d3, bH + (uint32_t)(((addrB0 ^ (u * 32)) + bofs)));
                Bfh[2*u][0] = d0; Bfh[2*u][1] = d1;
                Bfh[2*u+1][0] = d2; Bfh[2*u+1][1] = d3;
            }
            #pragma unroll
            for (int mt = 0; mt < MT; mt++)
                #pragma unroll
                for (int nt = 0; nt < 4; nt++)
                    mma_bf16(acc[mt][nt], Afh[mt], Bfh[nt]);

            #pragma unroll
            for (int u = 0; u < 2; u++) {
                uint32_t d0, d1, d2, d3;
                LDSM4T(d0, d1, d2, d3, bL + (uint32_t)(((addrB0 ^ (u * 32)) + bofs)));
                uint32_t Bfl0[2] = {d0, d1}, Bfl1[2] = {d2, d3};
                #pragma unroll
                for (int mt = 0; mt < MT; mt++) {
                    mma_bf16(acc[mt][2*u],   Afh[mt], Bfl0);
                    mma_bf16(acc[mt][2*u+1], Afh[mt], Bfl1);
                }
            }
            #pragma unroll
            for (int mt = 0; mt < MT; mt++) {
                uint32_t Afl[4];
                LDSM4(Afl[0], Afl[1], Afl[2], Afl[3],
                      aL + (uint32_t)(((addrA0 + mt * 1024) ^ axor)));
                #pragma unroll
                for (int nt = 0; nt < 4; nt++)
                    mma_bf16(acc[mt][nt], Afl, Bfh[nt]);
            }
        }
        __syncthreads();
    }

    float* Cw = Cf ? (Cf + offC) : nullptr;
    bf16* Chw = Chp ? (Chp + offC) : nullptr;
    bf16* Clw = Clp ? (Clp + offC) : nullptr;
    #pragma unroll
    for (int mt = 0; mt < MT; mt++) {
        int r0 = rowBase + wm * (TM / 2) + mt * 16 + g;
        #pragma unroll
        for (int half = 0; half < 2; half++) {
            int r = r0 + half * 8;
            if (r >= Mr) continue;
            #pragma unroll
            for (int nt = 0; nt < 4; nt++) {
                int c = colBase + wn * 32 + nt * 8 + tg * 2;
                if (c >= Nc) continue;
                float v0 = acc[mt][nt][half * 2];
                float v1 = acc[mt][nt][half * 2 + 1];
                size_t o = (size_t)r * ldc + c;
                if (Cw) { Cw[o] = v0; Cw[o + 1] = v1; }
                if (Chw) {
                    uint32_t lv, hv = pack_split_hi(v0, v1, lv);
                    *(uint32_t*)(Chw + o) = hv;
                    *(uint32_t*)(Clw + o) = lv;
                }
            }
        }
    }
}

template<int TM>
static void gemm(const bf16* Ah, const bf16* Al, const bf16* Bh, const bf16* Bl,
                 float* Cf, bf16* Chp, bf16* Clp,
                 int Mr, int Nc, int K, int lda, int ldb, int ldc,
                 int batch, int zdiv,
                 long long sA1, long long sA2, long long sB1, long long sB2,
                 long long sC1, long long sC2)
{
    dim3 grid((Nc + 127) / 128, (Mr + TM - 1) / TM, batch);
    gemm_kernel<TM><<<grid, 256, 2 * (TM * 128 + 16384)>>>(Ah, Al, Bh, Bl, Cf, Chp, Clp,
        Mr, Nc, K, lda, ldb, ldc, zdiv, sA1, sA2, sB1, sB2, sC1, sC2);
}

// ---------------- prep kernels ----------------
__global__ void split_kernel(const float* __restrict__ in, bf16* __restrict__ hi,
                             bf16* __restrict__ lo, size_t n) {
    size_t i = (size_t)blockIdx.x * blockDim.x + threadIdx.x;
    if (i >= n) return;
    bf16 h, l; split_bf(in[i], h, l);
    hi[i] = h; lo[i] = l;
}

__global__ void prep_deg_kernel(const int* __restrict__ s2w) {
    int idx = blockIdx.x * blockDim.x + threadIdx.x;
    if (idx < BS * NN) {
        const int* row = s2w + (size_t)idx * EE;
        int s = 1;
        for (int e = 0; e < EE; e++) s += row[e];
        g_invD[idx] = 1.f / (float)s;
    } else if (idx < BS * NN + BS * MM) {
        int t = idx - BS * NN;
        int m = t % MM, b = t / MM;
        if (m == 0) g_invB[t] = 1.f / (float)NN;
        else {
            int s = 0;
            for (int n = 0; n < NN; n++) s += s2w[((size_t)(b * NN + n)) * EE + (m - 1)];
            g_invB[t] = (s > 0) ? 1.f / (float)s : 0.f;
        }
    }
}

__global__ void prep_anorm_kernel(const int* __restrict__ aug,
                                  const int* __restrict__ punct) {
    int t = blockIdx.x * blockDim.x + threadIdx.x;
    if (t >= 2 * BS * NN) return;
    int j = t % NN;
    int b = (t / NN) % BS;
    int r = t / (NN * BS);
    int cnt = 0;
    for (int i = 0; i < NN; i++) {
        int a = aug[((size_t)(b * NN + i)) * NN + j];
        int v = r ? a : (punct[((size_t)(b * NN + i)) * NN + j] * (1 - a));
        cnt += v;
    }
    float val = cnt ? 1.f / (float)cnt : 0.f;
    bf16 vh, vl; split_bf(val, vh, vl);
    size_t base = ((size_t)(r * BS + b) * NN + j) * NN;
    for (int i = 0; i < NN; i++) {
        int a = aug[((size_t)(b * NN + i)) * NN + j];
        int v = r ? a : (punct[((size_t)(b * NN + i)) * NN + j] * (1 - a));
        g_Anh[base + i] = v ? vh : (bf16)__float2bfloat16(0.f);
        g_Anl[base + i] = v ? vl : (bf16)__float2bfloat16(0.f);
    }
}

// ---------------- attention path ----------------
// vx[h,k] = sum_c w_lin[l][k, h*C+c] * att_x[h,c]; ve likewise with att_e.
__global__ void compute_v_kernel(const float* __restrict__ wl,
                                 const float* __restrict__ attx,
                                 const float* __restrict__ atte) {
    int gw = (blockIdx.x * blockDim.x + threadIdx.x) >> 5;
    int lane = threadIdx.x & 31;
    if (gw >= 2 * HH * CC) return;
    int sel = gw / (HH * CC);
    int rem = gw % (HH * CC);
    int h = rem / CC, k = rem % CC;
    const float* att = (sel ? atte : attx) + h * CC;
    const float* row = wl + (size_t)k * (HH * CC) + h * CC;
    float acc = 0.f;
    for (int c = lane; c < CC; c += 32) acc += row[c] * att[c];
    #pragma unroll
    for (int o = 16; o; o >>= 1) acc += __shfl_xor_sync(0xffffffffu, acc, o);
    if (lane == 0) (sel ? g_ve : g_vx)[h * CC + k] = acc;
}

__global__ void ae_kernel(const float* __restrict__ pooled,
                          const float* __restrict__ svo) {
    int bm = blockIdx.x;
    int h = threadIdx.x >> 5, lane = threadIdx.x & 31;
    int b = bm / MM, m = bm % MM;
    const float* e = (m == 0) ? (pooled + (size_t)b * CC)
                              : (svo + ((size_t)(b * EE + (m - 1))) * CC);
    const float* v = g_ve + h * CC;
    float acc = 0.f;
    for (int c = lane; c < CC; c += 32) acc += e[c] * v[c];
    #pragma unroll
    for (int o = 16; o; o >>= 1) acc += __shfl_xor_sync(0xffffffffu, acc, o);
    if (lane == 0) g_ae[bm * HH + h] = acc;
}

// a_n inline + masked softmax. Writes:
//  m>=1: amn planes rows 1..64 ([z,MM,NN]); invB-scaled anm planes at j=m-1 ([z,NN,64])
//  m==0: g_amn0f (unscaled fp32), g_anm0f (invB-scaled fp32)
__global__ void alpha_kernel(const float* __restrict__ Xf, const int* __restrict__ s2w) {
    int bn = blockIdx.x;
    int b = bn >> 8, n = bn & 255;
    int h = threadIdx.x >> 5, lane = threadIdx.x & 31;
    const float* x = Xf + (size_t)bn * CC;
    const float* v = g_vx + h * CC;
    float anv = 0.f;
    for (int c = lane; c < CC; c += 32) anv += x[c] * v[c];
    #pragma unroll
    for (int o = 16; o; o >>= 1) anv += __shfl_xor_sync(0xffffffffu, anv, o);

    float vv3[3]; int ok[3];
    #pragma unroll
    for (int s = 0; s < 3; s++) {
        int m = lane + s * 32;
        float vv = -1e30f; int o = 0;
        if (m < MM) {
            o = (m == 0) || (s2w[(size_t)bn * EE + (m - 1)] != 0);
            if (o) {
                float xx = anv + g_ae[(b * MM + m) * HH + h];
                vv = (xx > 0.f) ? xx : 0.2f * xx;
            }
        }
        vv3[s] = vv; ok[s] = o;
    }
    float mx = fmaxf(vv3[0], fmaxf(vv3[1], vv3[2]));
    #pragma unroll
    for (int o = 16; o; o >>= 1) mx = fmaxf(mx, __shfl_xor_sync(0xffffffffu, mx, o));
    float e3[3]; float sum = 0.f;
    #pragma unroll
    for (int s = 0; s < 3; s++) { e3[s] = ok[s] ? expf(vv3[s] - mx) : 0.f; sum += e3[s]; }
    #pragma unroll
    for (int o = 16; o; o >>= 1) sum += __shfl_xor_sync(0xffffffffu, sum, o);
    float inv = 1.f / sum;
    size_t z = (size_t)(b * HH + h);
    #pragma unroll
    for (int s = 0; s < 3; s++) {
        int m = lane + s * 32;
        if (m < MM) {
            float a = e3[s] * inv;
            float as = a * g_invB[b * MM + m];
            if (m == 0) {
                g_amn0f[z * NN + n] = a;
                g_anm0f[z * NN + n] = as;
            } else {
                bf16 hb, lb;
                split_bf(a, hb, lb);
                size_t o1 = (z * MM + m) * NN + n;
                g_amnh[o1] = hb; g_amnl[o1] = lb;
                split_bf(as, hb, lb);
                size_t o2 = (z * NN + n) * EE + (m - 1);
                g_anmh[o2] = hb; g_anml[o2] = lb;
            }
        }
    }
}

// t0[z,c] = sum_n alpha0[z,n] * x[b,n,c]   (fp32)
__global__ void t0_kernel(const float* __restrict__ Xf) {
    int z = blockIdx.x;
    int b = z >> 2;
    int c = blockIdx.y * 128 + threadIdx.x;
    __shared__ float a[NN];
    for (int i = threadIdx.x; i < NN; i += 128) a[i] = g_amn0f[z * NN + i];
    __syncthreads();
    const float* x = Xf + (size_t)b * NN * CC + c;
    float acc = 0.f;
    #pragma unroll 4
    for (int n = 0; n < NN; n++) acc += a[n] * x[(size_t)n * CC];
    g_t0[z * CC + c] = acc;
}

// msg0[z,c] = sum_k t0[z,k] * wl[k, h*CC+c]   (fp32)
__global__ void msg0_kernel(const float* __restrict__ wl) {
    int z = blockIdx.x;
    int h = z & 3;
    int c = blockIdx.y * 128 + threadIdx.x;
    __shared__ float t0s[CC];
    for (int i = threadIdx.x; i < CC; i += 128) t0s[i] = g_t0[z * CC + i];
    __syncthreads();
    const float* w = wl + (size_t)h * CC + c;
    float acc = 0.f;
    #pragma unroll 4
    for (int k = 0; k < CC; k++) acc += t0s[k] * w[(size_t)k * (HH * CC)];
    g_msg0[z * CC + c] = acc;
}

// head mean + m0 rank-1 + invD + bias + relu
__global__ void finalize_h_kernel(float* __restrict__ out, const float* __restrict__ bias) {
    int bn = blockIdx.x; int c = threadIdx.x;
    int b = bn >> 8, n = bn & 255;
    float s = 0.f;
    #pragma unroll
    for (int h = 0; h < HH; h++) {
        int z = b * HH + h;
        s += g_ohp[((size_t)z * NN + n) * CC + c];
        s += g_anm0f[z * NN + n] * g_msg0[z * CC + c];
    }
    float v = s * 0.25f * g_invD[bn] + bias[c];
    v = (v > 0.f) ? v : 0.f;
    size_t o = (size_t)bn * CC + c;
    out[o] = v;
    bf16 hb, lb; split_bf(v, hb, lb);
    g_xhh[o] = hb; g_xhl[o] = lb;
}

__global__ void combine_rgcn_kernel(float* __restrict__ out, const float* __restrict__ bias) {
    int bj = blockIdx.x; int c = threadIdx.x;
    size_t o = (size_t)bj * CC + c;
    float v = g_agg[o] + g_agg[(size_t)BS * NN * CC + o] + g_xroot[o] + bias[c];
    v = (v > 0.f) ? v : 0.f;
    out[o] = v;
    bf16 hb, lb; split_bf(v, hb, lb);
    g_xrh[o] = hb; g_xrl[o] = lb;
}

// ---------------- info exchange ----------------
__global__ void build_ctx_kernel(const float* __restrict__ xr, const float* __restrict__ xh) {
    int idx = blockIdx.x * blockDim.x + threadIdx.x;
    if (idx >= BS * 2 * CC) return;
    int c = idx % (2 * CC); int b = idx / (2 * CC);
    g_ctx[idx] = (c < CC) ? xr[(size_t)b * NN * CC + c]
                          : xh[(size_t)b * NN * CC + (c - CC)];
}

__global__ void ie_gemm_kernel(const float* __restrict__ in, const float* __restrict__ W,
                               const float* __restrict__ bias, float* __restrict__ out,
                               int relu) {
    __shared__ float s_in[2 * CC];
    int b = blockIdx.y;
    int j = blockIdx.x * 128 + threadIdx.x;
    for (int t = threadIdx.x; t < 2 * CC; t += 128) s_in[t] = in[b * 2 * CC + t];
    __syncthreads();
    float a0 = 0.f, a1 = 0.f, a2 = 0.f, a3 = 0.f;
    for (int k = 0; k < 2 * CC; k += 4) {
        a0 += s_in[k + 0] * W[(size_t)(k + 0) * (2 * CC) + j];
        a1 += s_in[k + 1] * W[(size_t)(k + 1) * (2 * CC) + j];
        a2 += s_in[k + 2] * W[(size_t)(k + 2) * (2 * CC) + j];
        a3 += s_in[k + 3] * W[(size_t)(k + 3) * (2 * CC) + j];
    }
    float acc = (a0 + a1) + (a2 + a3) + bias[j];
    if (relu) acc = (acc > 0.f) ? acc : 0.f;
    out[b * 2 * CC + j] = acc;
}

__global__ void writeback_kernel(float* __restrict__ xr, float* __restrict__ xh) {
    int idx = blockIdx.x * blockDim.x + threadIdx.x;
    if (idx >= BS * 2 * CC) return;
    int c = idx % (2 * CC); int b = idx / (2 * CC);
    float v = g_ctx2[idx];
    bf16 hb, lb; split_bf(v, hb, lb);
    if (c < CC) {
        size_t o = (size_t)b * NN * CC + c;
        xr[o] = v; g_xrh[o] = hb; g_xrl[o] = lb;
    } else {
        size_t o = (size_t)b * NN * CC + (c - CC);
        xh[o] = v; g_xhh[o] = hb; g_xhl[o] = lb;
    }
}

// ---------------- launch ----------------
#define SYM(p, s) cudaGetSymbolAddress((void**)&p, s)

extern "C" void kernel_launch(void* const* d_in, const int* in_sizes, int n_in,
                              void* d_out, int out_size) {
    const float* spans  = (const float*)d_in[0];
    const float* svo    = (const float*)d_in[1];
    const float* pooled = (const float*)d_in[2];
    const int*   s2w    = (const int*)d_in[3];
    const int*   aug    = (const int*)d_in[4];
    const int*   punct  = (const int*)d_in[5];
    const float* w_rel  = (const float*)d_in[6];
    const float* w_root = (const float*)d_in[7];
    const float* b_rgcn = (const float*)d_in[8];
    const float* w_lin  = (const float*)d_in[9];
    const float* att_x  = (const float*)d_in[10];
    const float* att_e  = (const float*)d_in[11];
    const float* b_hgcn = (const float*)d_in[12];
    const float* ie_w1  = (const float*)d_in[13];
    const float* ie_b1  = (const float*)d_in[14];
    const float* ie_w2  = (const float*)d_in[15];
    const float* ie_b2  = (const float*)d_in[16];
    float* out = (float*)d_out;

    cudaFuncSetAttribute(gemm_kernel<128>, cudaFuncAttributeMaxDynamicSharedMemorySize,
                         2 * (128 * 128 + 16384));
    cudaFuncSetAttribute(gemm_kernel<64>, cudaFuncAttributeMaxDynamicSharedMemorySize,
                         2 * (64 * 128 + 16384));

    float *p_ohp, *p_agg, *p_xroot, *p_xr, *p_xh, *p_ctx, *p_h1, *p_ctx2;
    SYM(p_ohp, g_ohp); SYM(p_agg, g_agg); SYM(p_xroot, g_xroot);
    SYM(p_xr, g_xr); SYM(p_xh, g_xh);
    SYM(p_ctx, g_ctx); SYM(p_h1, g_h1); SYM(p_ctx2, g_ctx2);

    bf16 *x0h,*x0l,*wlh,*wll,*wrh,*wrl,*wth,*wtl;
    bf16 *amnh,*amnl,*anmh,*anml,*th,*tl,*msgh,*msgl,*xwh,*xwl,*Anh,*Anl;
    bf16 *xrh,*xrl,*xhh,*xhl;
    SYM(x0h, g_x0h); SYM(x0l, g_x0l);
    SYM(wlh, g_wlh); SYM(wll, g_wll); SYM(wrh, g_wrh); SYM(wrl, g_wrl);
    SYM(wth, g_wth); SYM(wtl, g_wtl);
    SYM(amnh, g_amnh); SYM(amnl, g_amnl);
    SYM(anmh, g_anmh); SYM(anml, g_anml);
    SYM(th, g_th); SYM(tl, g_tl);
    SYM(msgh, g_msgh); SYM(msgl, g_msgl);
    SYM(xwh, g_xwh); SYM(xwl, g_xwl); SYM(Anh, g_Anh); SYM(Anl, g_Anl);
    SYM(xrh, g_xrh); SYM(xrl, g_xrl); SYM(xhh, g_xhh); SYM(xhl, g_xhl);

    // ---- layer-invariant prep ----
    {
        size_t n;
        n = (size_t)BS*NN*CC;
        split_kernel<<<(int)((n+255)/256), 256>>>(spans, x0h, x0l, n);
        n = (size_t)LL*CC*HH*CC;
        split_kernel<<<(int)((n+255)/256), 256>>>(w_lin, wlh, wll, n);
        n = (size_t)LL*2*CC*CC;
        split_kernel<<<(int)((n+255)/256), 256>>>(w_rel, wrh, wrl, n);
        n = (size_t)LL*CC*CC;
        split_kernel<<<(int)((n+255)/256), 256>>>(w_root, wth, wtl, n);
    }
    prep_deg_kernel<<<(BS * NN + BS * MM + 127) / 128, 128>>>(s2w);
    prep_anorm_kernel<<<(2 * BS * NN + 127) / 128, 128>>>(aug, punct);

    const float* Axh_f = spans;            // fp32 x_h (for alpha a_n and t0)
    const bf16 *Axh_h = x0h, *Axh_l = x0l; // x_h planes
    const bf16 *Axr_h = x0h, *Axr_l = x0l; // x_r planes

    for (int l = 0; l < LL; l++) {
        float* xr_out = (l == LL - 1) ? out : p_xr;
        float* xh_out = (l == LL - 1) ? out + (size_t)BS * NN * CC : p_xh;
        const float* wlf = w_lin + (size_t)l * CC * HH * CC;
        const bf16* wlhp = wlh + (size_t)l * CC * HH * CC;
        const bf16* wllp = wll + (size_t)l * CC * HH * CC;

        // ---- HypergraphConv (att-vector folded, m=0 separated) ----
        compute_v_kernel<<<(2 * HH * CC * 32 + 255) / 256, 256>>>(
            wlf, att_x + (size_t)l * HH * CC, att_e + (size_t)l * HH * CC);
        ae_kernel<<<BS * MM, 128>>>(pooled, svo);
        alpha_kernel<<<BS * NN, 128>>>(Axh_f, s2w);
        t0_kernel<<<dim3(BS * HH, 4), 128>>>(Axh_f);
        // t rows 1..64: [64,512] = amn[1:65] @ x_h, batch (b,h)   (exact 64-tile)
        gemm<64>(amnh + NN, amnl + NN, Axh_h, Axh_l, nullptr, th + CC, tl + CC,
             64, CC, NN, NN, CC, CC, BS*HH, HH,
             (long long)HH*MM*NN, (long long)MM*NN,
             (long long)NN*CC, 0,
             (long long)HH*MM*CC, (long long)MM*CC);
        // msg rows 1..64: [64,512] = t[1:65] @ Wl[:,h-block], batch (b,h)
        gemm<64>(th + CC, tl + CC, wlhp, wllp, nullptr, msgh + CC, msgl + CC,
             64, CC, CC, CC, HH*CC, CC, BS*HH, HH,
             (long long)HH*MM*CC, (long long)MM*CC,
             0, (long long)CC,
             (long long)HH*MM*CC, (long long)MM*CC);
        msg0_kernel<<<dim3(BS * HH, 4), 128>>>(wlf);
        // ohp = anm(64-wide) @ msg[1:65], batch (b,h)
        gemm<128>(anmh, anml, msgh + CC, msgl + CC, p_ohp, nullptr, nullptr,
             NN, CC, EE, EE, CC, CC, BS*HH, HH,
             (long long)HH*NN*EE, (long long)NN*EE,
             (long long)HH*MM*CC, (long long)MM*CC,
             (long long)HH*NN*CC, (long long)NN*CC);
        finalize_h_kernel<<<BS*NN, CC>>>(xh_out, b_hgcn + (size_t)l*CC);

        // ---- RGCN ----
        gemm<128>(Axr_h, Axr_l, wrh + (size_t)l*2*CC*CC, wrl + (size_t)l*2*CC*CC,
             nullptr, xwh, xwl,
             BS*NN, CC, CC, CC, CC, CC, 2, 1,
             0, 0, (long long)CC*CC, 0, (long long)BS*NN*CC, 0);
        gemm<128>(Axr_h, Axr_l, wth + (size_t)l*CC*CC, wtl + (size_t)l*CC*CC,
             p_xroot, nullptr, nullptr,
             BS*NN, CC, CC, CC, CC, CC, 1, 1, 0,0,0,0,0,0);
        gemm<128>(Anh, Anl, xwh, xwl, p_agg, nullptr, nullptr,
             NN, CC, NN, NN, CC, CC, 2*BS, BS,
             (long long)BS*NN*NN, (long long)NN*NN,
             (long long)BS*NN*CC, (long long)NN*CC,
             (long long)BS*NN*CC, (long long)NN*CC);
        combine_rgcn_kernel<<<BS*NN, CC>>>(xr_out, b_rgcn + (size_t)l*CC);

        // ---- info exchange (row 0) ----
        build_ctx_kernel<<<(BS*2*CC + 255)/256, 256>>>(xr_out, xh_out);
        ie_gemm_kernel<<<dim3(2*CC/128, BS), 128>>>(
            p_ctx, ie_w1 + (size_t)l*2*CC*2*CC, ie_b1 + (size_t)l*2*CC, p_h1, 1);
        ie_gemm_kernel<<<dim3(2*CC/128, BS), 128>>>(
            p_h1, ie_w2 + (size_t)l*2*CC*2*CC, ie_b2 + (size_t)l*2*CC, p_ctx2, 0);
        writeback_kernel<<<(BS*2*CC + 255)/256, 256>>>(xr_out, xh_out);

        Axh_f = xh_out;
        Axh_h = xhh; Axh_l = xhl;
        Axr_h = xrh; Axr_l = xrl;
    }
    (void)in_sizes; (void)n_in; (void)out_size;
}

// round 12
// speedup vs baseline: 1.0517x; 1.0517x over previous
#include <cuda_runtime.h>
#include <cuda_bf16.h>
#include <math.h>
#include <stdint.h>

#define BS 32
#define NN 256
#define EE 64
#define CC 512
#define HH 4
#define LL 2
#define MM 65
#define ALD 80   // padded lda for alpha_nm (160B rows, 16B aligned)

typedef __nv_bfloat16 bf16;

// ---------------- fp32 scratch ----------------
__device__ float g_ohp[(size_t)BS*HH*NN*CC];
__device__ float g_agg[(size_t)2*BS*NN*CC];
__device__ float g_xr[(size_t)BS*NN*CC];
__device__ float g_xh[(size_t)BS*NN*CC];
__device__ float g_ae[BS*MM*HH];
__device__ float g_vx[HH*CC];
__device__ float g_ve[HH*CC];
__device__ float g_invD[BS*NN];
__device__ float g_invB[BS*MM];
__device__ float g_ctx[BS*2*CC];
__device__ float g_h1[BS*2*CC];
__device__ float g_ctx2[BS*2*CC];

// ---------------- bf16 hi/lo planes ----------------
__device__ bf16 g_x0h[(size_t)BS*NN*CC],      g_x0l[(size_t)BS*NN*CC];
__device__ bf16 g_wlh[(size_t)LL*CC*HH*CC],   g_wll[(size_t)LL*CC*HH*CC];
__device__ bf16 g_wcth[(size_t)LL*CC*3*CC],   g_wctl[(size_t)LL*CC*3*CC];  // [wrel0|wrel1|wroot]
__device__ bf16 g_amnh[(size_t)BS*HH*MM*NN],  g_amnl[(size_t)BS*HH*MM*NN];
__device__ bf16 g_anmh[(size_t)BS*HH*NN*ALD], g_anml[(size_t)BS*HH*NN*ALD];
__device__ bf16 g_th[(size_t)BS*HH*MM*CC],    g_tl[(size_t)BS*HH*MM*CC];
__device__ bf16 g_msgh[(size_t)BS*HH*MM*CC],  g_msgl[(size_t)BS*HH*MM*CC];
__device__ bf16 g_xch[(size_t)BS*NN*3*CC],    g_xcl[(size_t)BS*NN*3*CC];   // [xw0|xw1|xroot]
__device__ bf16 g_Anh[(size_t)2*BS*NN*NN],    g_Anl[(size_t)2*BS*NN*NN];
__device__ bf16 g_xrh[(size_t)BS*NN*CC],      g_xrl[(size_t)BS*NN*CC];
__device__ bf16 g_xhh[(size_t)BS*NN*CC],      g_xhl[(size_t)BS*NN*CC];

// ---------------- helpers ----------------
__device__ __forceinline__ void split_bf(float x, bf16& h, bf16& l) {
    h = __float2bfloat16(x);
    l = __float2bfloat16(x - __bfloat162float(h));
}
__device__ __forceinline__ uint32_t pack_split_hi(float a, float b, uint32_t& lo_out) {
    bf16 h0, l0, h1, l1;
    split_bf(a, h0, l0); split_bf(b, h1, l1);
    __nv_bfloat162 hp; hp.x = h0; hp.y = h1;
    __nv_bfloat162 lp; lp.x = l0; lp.y = l1;
    uint32_t hv, lv;
    __builtin_memcpy(&hv, &hp, 4); __builtin_memcpy(&lv, &lp, 4);
    lo_out = lv; return hv;
}
__device__ __forceinline__ void mma_bf16(float* c, const uint32_t* a, const uint32_t* b) {
    asm volatile(
        "mma.sync.aligned.m16n8k16.row.col.f32.bf16.bf16.f32 "
        "{%0,%1,%2,%3}, {%4,%5,%6,%7}, {%8,%9}, {%0,%1,%2,%3};\n"
        : "+f"(c[0]), "+f"(c[1]), "+f"(c[2]), "+f"(c[3])
        : "r"(a[0]), "r"(a[1]), "r"(a[2]), "r"(a[3]), "r"(b[0]), "r"(b[1]));
}
__device__ __forceinline__ void cp16(uint32_t dst, const void* src, int sz) {
    asm volatile("cp.async.cg.shared.global [%0], [%1], 16, %2;\n"
                 :: "r"(dst), "l"(src), "r"(sz));
}
#define LDSM4(d0,d1,d2,d3,a) \
    asm volatile("ldmatrix.sync.aligned.m8n8.x4.shared.b16 {%0,%1,%2,%3}, [%4];" \
                 : "=r"(d0),"=r"(d1),"=r"(d2),"=r"(d3) : "r"(a))
#define LDSM4T(d0,d1,d2,d3,a) \
    asm volatile("ldmatrix.sync.aligned.m8n8.x4.trans.shared.b16 {%0,%1,%2,%3}, [%4];" \
                 : "=r"(d0),"=r"(d1),"=r"(d2),"=r"(d3) : "r"(a))

// ================= mma.sync split-bf16 GEMM, tile 128x128x32, 3-stage =================
// C = (Ah+Al)@(Bh+Bl) via AhBh + AhBl + AlBh, fp32 accum. 256 threads, 8 warps
// (2 x 4), warp tile 64x32. Triple-buffered cp.async + ldmatrix + XOR swizzle.
#define STG_BYTES 32768   // per stage: Ah 8K | Al 8K | Bh 8K | Bl 8K
#define NSTG 3

__global__ __launch_bounds__(256, 2)
void gemm_kernel(const bf16* __restrict__ Ah, const bf16* __restrict__ Al,
                 const bf16* __restrict__ Bh, const bf16* __restrict__ Bl,
                 float* __restrict__ Cf, bf16* __restrict__ Chp, bf16* __restrict__ Clp,
                 int Mr, int Nc, int K, int lda, int ldb, int ldc,
                 int zdiv,
                 long long sA1, long long sA2,
                 long long sB1, long long sB2,
                 long long sC1, long long sC2)
{
    extern __shared__ __align__(128) unsigned char smem_raw[];
    uint32_t smem = (uint32_t)__cvta_generic_to_shared(smem_raw);

    int z = blockIdx.z;
    int z1 = z / zdiv, z2 = z % zdiv;
    long long offA = z1 * sA1 + z2 * sA2;
    long long offB = z1 * sB1 + z2 * sB2;
    long long offC = z1 * sC1 + z2 * sC2;
    Ah += offA; Al += offA; Bh += offB; Bl += offB;

    const int tid = threadIdx.x;
    const int warp = tid >> 5, lane = tid & 31;
    const int wm = warp >> 2, wn = warp & 3;
    const int g = lane >> 2, tg = lane & 3;
    const int rowBase = blockIdx.y * 128;
    const int colBase = blockIdx.x * 128;

    int am[2], ac[2], adst[2];
    int bk[2], bc[2], bdst[2];
    #pragma unroll
    for (int i = 0; i < 2; i++) {
        int q = i * 256 + tid;
        am[i] = q >> 2; ac[i] = q & 3;
        adst[i] = am[i] * 64 + ((ac[i] ^ (am[i] & 3)) << 4);
        bk[i] = q >> 4; bc[i] = q & 15;
        bdst[i] = bk[i] * 256 + ((bc[i] ^ (bk[i] & 7)) << 4);
    }

    int mloc = wm * 64 + (lane & 15);
    int addrA0 = mloc * 64 + (((lane >> 4) ^ (mloc & 3)) << 4);
    int kB = lane & 15;
    int cB0 = wn * 4 + (lane >> 4);
    int addrB0 = kB * 256 + ((cB0 ^ (kB & 7)) << 4);

    float acc[4][4][4];
    #pragma unroll
    for (int i = 0; i < 4; i++)
        #pragma unroll
        for (int j = 0; j < 4; j++)
            #pragma unroll
            for (int r = 0; r < 4; r++) acc[i][j][r] = 0.f;

    const int S = (K + 31) / 32;

    auto copy_stage = [&](int s, int buf) {
        int k0 = s * 32;
        uint32_t base = smem + buf * STG_BYTES;
        #pragma unroll
        for (int i = 0; i < 2; i++) {
            int gr = rowBase + am[i];
            int kk = k0 + ac[i] * 8;
            int rem = (gr < Mr) ? (K - kk) * 2 : 0;
            int sz = rem < 0 ? 0 : (rem > 16 ? 16 : rem);
            int grc = (gr < Mr) ? gr : 0;
            int kkc = (sz > 0) ? kk : 0;
            size_t so = (size_t)grc * lda + kkc;
            cp16(base + adst[i],        Ah + so, sz);
            cp16(base + 8192 + adst[i], Al + so, sz);
        }
        #pragma unroll
        for (int i = 0; i < 2; i++) {
            int kk = k0 + bk[i];
            int gc = colBase + bc[i] * 8;
            int ok = (kk < K) && (gc < Nc);
            int kkc = ok ? kk : 0;
            int gcc = ok ? gc : 0;
            size_t so = (size_t)kkc * ldb + gcc;
            cp16(base + 16384 + bdst[i], Bh + so, ok ? 16 : 0);
            cp16(base + 24576 + bdst[i], Bl + so, ok ? 16 : 0);
        }
    };

    // prologue: stages 0,1
    for (int s = 0; s < 2 && s < S; s++) {
        copy_stage(s, s);
        asm volatile("cp.async.commit_group;\n");
    }

    for (int s = 0; s < S; s++) {
        if (s + 2 < S) {
            copy_stage(s + 2, (s + 2) % NSTG);
            asm volatile("cp.async.commit_group;\n");
        }
        int pend = S - 1 - s; if (pend > 2) pend = 2;
        if (pend == 2)      asm volatile("cp.async.wait_group 2;\n");
        else if (pend == 1) asm volatile("cp.async.wait_group 1;\n");
        else                asm volatile("cp.async.wait_group 0;\n");
        __syncthreads();

        uint32_t aH = smem + (s % NSTG) * STG_BYTES;
        uint32_t aL = aH + 8192;
        uint32_t bH = aH + 16384;
        uint32_t bL = aH + 24576;

        #pragma unroll
        for (int ks = 0; ks < 2; ks++) {
            int axor = ks * 32;
            int bofs = ks * 4096;
            uint32_t Afh[4][4], Bfh[4][2];
            #pragma unroll
            for (int mt = 0; mt < 4; mt++)
                LDSM4(Afh[mt][0], Afh[mt][1], Afh[mt][2], Afh[mt][3],
                      aH + (uint32_t)(((addrA0 + mt * 1024) ^ axor)));
            #pragma unroll
            for (int u = 0; u < 2; u++) {
                uint32_t d0, d1, d2, d3;
                LDSM4T(d0, d1, d2, d3, bH + (uint32_t)(((addrB0 ^ (u * 32)) + bofs)));
                Bfh[2*u][0] = d0; Bfh[2*u][1] = d1;
                Bfh[2*u+1][0] = d2; Bfh[2*u+1][1] = d3;
            }
            #pragma unroll
            for (int mt = 0; mt < 4; mt++)
                #pragma unroll
                for (int nt = 0; nt < 4; nt++)
                    mma_bf16(acc[mt][nt], Afh[mt], Bfh[nt]);

            #pragma unroll
            for (int u = 0; u < 2; u++) {
                uint32_t d0, d1, d2, d3;
                LDSM4T(d0, d1, d2, d3, bL + (uint32_t)(((addrB0 ^ (u * 32)) + bofs)));
                uint32_t Bfl0[2] = {d0, d1}, Bfl1[2] = {d2, d3};
                #pragma unroll
                for (int mt = 0; mt < 4; mt++) {
                    mma_bf16(acc[mt][2*u],   Afh[mt], Bfl0);
                    mma_bf16(acc[mt][2*u+1], Afh[mt], Bfl1);
                }
            }
            #pragma unroll
            for (int mt = 0; mt < 4; mt++) {
                uint32_t Afl[4];
                LDSM4(Afl[0], Afl[1], Afl[2], Afl[3],
                      aL + (uint32_t)(((addrA0 + mt * 1024) ^ axor)));
                #pragma unroll
                for (int nt = 0; nt < 4; nt++)
                    mma_bf16(acc[mt][nt], Afl, Bfh[nt]);
            }
        }
        __syncthreads();
    }

    float* Cw = Cf ? (Cf + offC) : nullptr;
    bf16* Chw = Chp ? (Chp + offC) : nullptr;
    bf16* Clw = Clp ? (Clp + offC) : nullptr;
    #pragma unroll
    for (int mt = 0; mt < 4; mt++) {
        int r0 = rowBase + wm * 64 + mt * 16 + g;
        #pragma unroll
        for (int half = 0; half < 2; half++) {
            int r = r0 + half * 8;
            if (r >= Mr) continue;
            #pragma unroll
            for (int nt = 0; nt < 4; nt++) {
                int c = colBase + wn * 32 + nt * 8 + tg * 2;
                if (c >= Nc) continue;
                float v0 = acc[mt][nt][half * 2];
                float v1 = acc[mt][nt][half * 2 + 1];
                size_t o = (size_t)r * ldc + c;
                if (Cw) { Cw[o] = v0; Cw[o + 1] = v1; }
                if (Chw) {
                    uint32_t lv, hv = pack_split_hi(v0, v1, lv);
                    *(uint32_t*)(Chw + o) = hv;
                    *(uint32_t*)(Clw + o) = lv;
                }
            }
        }
    }
}

static void gemm(const bf16* Ah, const bf16* Al, const bf16* Bh, const bf16* Bl,
                 float* Cf, bf16* Chp, bf16* Clp,
                 int Mr, int Nc, int K, int lda, int ldb, int ldc,
                 int batch, int zdiv,
                 long long sA1, long long sA2, long long sB1, long long sB2,
                 long long sC1, long long sC2)
{
    dim3 grid((Nc + 127) / 128, (Mr + 127) / 128, batch);
    gemm_kernel<<<grid, 256, NSTG * STG_BYTES>>>(Ah, Al, Bh, Bl, Cf, Chp, Clp,
        Mr, Nc, K, lda, ldb, ldc, zdiv, sA1, sA2, sB1, sB2, sC1, sC2);
}

// ---------------- prep kernels ----------------
__global__ void split_kernel(const float* __restrict__ in, bf16* __restrict__ hi,
                             bf16* __restrict__ lo, size_t n) {
    size_t i = (size_t)blockIdx.x * blockDim.x + threadIdx.x;
    if (i >= n) return;
    bf16 h, l; split_bf(in[i], h, l);
    hi[i] = h; lo[i] = l;
}

// wcat[l][k][j] = j<2C ? w_rel[l][j/C][k][j%C] : w_root[l][k][j-2C], split planes
__global__ void build_wcat_kernel(const float* __restrict__ w_rel,
                                  const float* __restrict__ w_root) {
    size_t idx = (size_t)blockIdx.x * blockDim.x + threadIdx.x;
    if (idx >= (size_t)LL * CC * 3 * CC) return;
    int j = (int)(idx % (3 * CC));
    int k = (int)((idx / (3 * CC)) % CC);
    int l = (int)(idx / ((size_t)CC * 3 * CC));
    float v;
    if (j < 2 * CC) {
        int r = j / CC, c = j % CC;
        v = w_rel[(((size_t)l * 2 + r) * CC + k) * CC + c];
    } else {
        v = w_root[((size_t)l * CC + k) * CC + (j - 2 * CC)];
    }
    bf16 h, lo; split_bf(v, h, lo);
    g_wcth[idx] = h; g_wctl[idx] = lo;
}

__global__ void prep_deg_kernel(const int* __restrict__ s2w) {
    int idx = blockIdx.x * blockDim.x + threadIdx.x;
    if (idx < BS * NN) {
        const int* row = s2w + (size_t)idx * EE;
        int s = 1;
        for (int e = 0; e < EE; e++) s += row[e];
        g_invD[idx] = 1.f / (float)s;
    } else if (idx < BS * NN + BS * MM) {
        int t = idx - BS * NN;
        int m = t % MM, b = t / MM;
        if (m == 0) g_invB[t] = 1.f / (float)NN;
        else {
            int s = 0;
            for (int n = 0; n < NN; n++) s += s2w[((size_t)(b * NN + n)) * EE + (m - 1)];
            g_invB[t] = (s > 0) ? 1.f / (float)s : 0.f;
        }
    }
}

__global__ void prep_anorm_kernel(const int* __restrict__ aug,
                                  const int* __restrict__ punct) {
    int t = blockIdx.x * blockDim.x + threadIdx.x;
    if (t >= 2 * BS * NN) return;
    int j = t % NN;
    int b = (t / NN) % BS;
    int r = t / (NN * BS);
    int cnt = 0;
    for (int i = 0; i < NN; i++) {
        int a = aug[((size_t)(b * NN + i)) * NN + j];
        int v = r ? a : (punct[((size_t)(b * NN + i)) * NN + j] * (1 - a));
        cnt += v;
    }
    float val = cnt ? 1.f / (float)cnt : 0.f;
    bf16 vh, vl; split_bf(val, vh, vl);
    size_t base = ((size_t)(r * BS + b) * NN + j) * NN;
    for (int i = 0; i < NN; i++) {
        int a = aug[((size_t)(b * NN + i)) * NN + j];
        int v = r ? a : (punct[((size_t)(b * NN + i)) * NN + j] * (1 - a));
        g_Anh[base + i] = v ? vh : (bf16)__float2bfloat16(0.f);
        g_Anl[base + i] = v ? vl : (bf16)__float2bfloat16(0.f);
    }
}

// ---------------- attention path (att-vector folding) ----------------
__global__ void compute_v_kernel(const float* __restrict__ wl,
                                 const float* __restrict__ attx,
                                 const float* __restrict__ atte) {
    int gw = (blockIdx.x * blockDim.x + threadIdx.x) >> 5;
    int lane = threadIdx.x & 31;
    if (gw >= 2 * HH * CC) return;
    int sel = gw / (HH * CC);
    int rem = gw % (HH * CC);
    int h = rem / CC, k = rem % CC;
    const float* att = (sel ? atte : attx) + h * CC;
    const float* row = wl + (size_t)k * (HH * CC) + h * CC;
    float acc = 0.f;
    for (int c = lane; c < CC; c += 32) acc += row[c] * att[c];
    #pragma unroll
    for (int o = 16; o; o >>= 1) acc += __shfl_xor_sync(0xffffffffu, acc, o);
    if (lane == 0) (sel ? g_ve : g_vx)[h * CC + k] = acc;
}

__global__ void ae_kernel(const float* __restrict__ pooled,
                          const float* __restrict__ svo) {
    int bm = blockIdx.x;
    int h = threadIdx.x >> 5, lane = threadIdx.x & 31;
    int b = bm / MM, m = bm % MM;
    const float* e = (m == 0) ? (pooled + (size_t)b * CC)
                              : (svo + ((size_t)(b * EE + (m - 1))) * CC);
    const float* v = g_ve + h * CC;
    float acc = 0.f;
    for (int c = lane; c < CC; c += 32) acc += e[c] * v[c];
    #pragma unroll
    for (int o = 16; o; o >>= 1) acc += __shfl_xor_sync(0xffffffffu, acc, o);
    if (lane == 0) g_ae[bm * HH + h] = acc;
}

// a_n inline + masked softmax; writes alpha_mn planes and invB-scaled alpha_nm planes
__global__ void alpha_kernel(const bf16* __restrict__ Xh, const bf16* __restrict__ Xl,
                             const int* __restrict__ s2w) {
    int bn = blockIdx.x;
    int b = bn >> 8, n = bn & 255;
    int h = threadIdx.x >> 5, lane = threadIdx.x & 31;
    const bf16* xh = Xh + (size_t)bn * CC;
    const bf16* xl = Xl + (size_t)bn * CC;
    const float* v = g_vx + h * CC;
    float anv = 0.f;
    for (int c = lane; c < CC; c += 32)
        anv += (__bfloat162float(xh[c]) + __bfloat162float(xl[c])) * v[c];
    #pragma unroll
    for (int o = 16; o; o >>= 1) anv += __shfl_xor_sync(0xffffffffu, anv, o);

    float vv3[3]; int ok[3];
    #pragma unroll
    for (int s = 0; s < 3; s++) {
        int m = lane + s * 32;
        float vv = -1e30f; int o = 0;
        if (m < MM) {
            o = (m == 0) || (s2w[(size_t)bn * EE + (m - 1)] != 0);
            if (o) {
                float x = anv + g_ae[(b * MM + m) * HH + h];
                vv = (x > 0.f) ? x : 0.2f * x;
            }
        }
        vv3[s] = vv; ok[s] = o;
    }
    float mx = fmaxf(vv3[0], fmaxf(vv3[1], vv3[2]));
    #pragma unroll
    for (int o = 16; o; o >>= 1) mx = fmaxf(mx, __shfl_xor_sync(0xffffffffu, mx, o));
    float e3[3]; float sum = 0.f;
    #pragma unroll
    for (int s = 0; s < 3; s++) { e3[s] = ok[s] ? expf(vv3[s] - mx) : 0.f; sum += e3[s]; }
    #pragma unroll
    for (int o = 16; o; o >>= 1) sum += __shfl_xor_sync(0xffffffffu, sum, o);
    float inv = 1.f / sum;
    size_t z = (size_t)(b * HH + h);
    #pragma unroll
    for (int s = 0; s < 3; s++) {
        int m = lane + s * 32;
        if (m < MM) {
            float a = e3[s] * inv;
            bf16 hb, lb;
            split_bf(a, hb, lb);
            size_t o1 = (z * MM + m) * NN + n;
            g_amnh[o1] = hb; g_amnl[o1] = lb;
            float as = a * g_invB[b * MM + m];
            split_bf(as, hb, lb);
            size_t o2 = (z * NN + n) * ALD + m;
            g_anmh[o2] = hb; g_anml[o2] = lb;
        }
    }
}

__global__ void finalize_h_kernel(float* __restrict__ out, const float* __restrict__ bias) {
    int bn = blockIdx.x; int c = threadIdx.x;
    int b = bn >> 8, n = bn & 255;
    float s = 0.f;
    #pragma unroll
    for (int h = 0; h < HH; h++)
        s += g_ohp[(((size_t)(b * HH + h)) * NN + n) * CC + c];
    float v = s * 0.25f * g_invD[bn] + bias[c];
    v = (v > 0.f) ? v : 0.f;
    size_t o = (size_t)bn * CC + c;
    out[o] = v;
    bf16 hb, lb; split_bf(v, hb, lb);
    g_xhh[o] = hb; g_xhl[o] = lb;
}

// agg0 + agg1 + xroot(from xcat planes) + bias, relu
__global__ void combine_rgcn_kernel(float* __restrict__ out, const float* __restrict__ bias) {
    int bj = blockIdx.x; int c = threadIdx.x;
    size_t o = (size_t)bj * CC + c;
    size_t xo = (size_t)bj * 3 * CC + 2 * CC + c;
    float xroot = __bfloat162float(g_xch[xo]) + __bfloat162float(g_xcl[xo]);
    float v = g_agg[o] + g_agg[(size_t)BS * NN * CC + o] + xroot + bias[c];
    v = (v > 0.f) ? v : 0.f;
    out[o] = v;
    bf16 hb, lb; split_bf(v, hb, lb);
    g_xrh[o] = hb; g_xrl[o] = lb;
}

// ---------------- info exchange ----------------
__global__ void build_ctx_kernel(const float* __restrict__ xr, const float* __restrict__ xh) {
    int idx = blockIdx.x * blockDim.x + threadIdx.x;
    if (idx >= BS * 2 * CC) return;
    int c = idx % (2 * CC); int b = idx / (2 * CC);
    g_ctx[idx] = (c < CC) ? xr[(size_t)b * NN * CC + c]
                          : xh[(size_t)b * NN * CC + (c - CC)];
}

__global__ void ie_gemm_kernel(const float* __restrict__ in, const float* __restrict__ W,
                               const float* __restrict__ bias, float* __restrict__ out,
                               int relu) {
    __shared__ float s_in[2 * CC];
    int b = blockIdx.y;
    int j = blockIdx.x * 128 + threadIdx.x;
    for (int t = threadIdx.x; t < 2 * CC; t += 128) s_in[t] = in[b * 2 * CC + t];
    __syncthreads();
    float a0 = 0.f, a1 = 0.f, a2 = 0.f, a3 = 0.f;
    for (int k = 0; k < 2 * CC; k += 4) {
        a0 += s_in[k + 0] * W[(size_t)(k + 0) * (2 * CC) + j];
        a1 += s_in[k + 1] * W[(size_t)(k + 1) * (2 * CC) + j];
        a2 += s_in[k + 2] * W[(size_t)(k + 2) * (2 * CC) + j];
        a3 += s_in[k + 3] * W[(size_t)(k + 3) * (2 * CC) + j];
    }
    float acc = (a0 + a1) + (a2 + a3) + bias[j];
    if (relu) acc = (acc > 0.f) ? acc : 0.f;
    out[b * 2 * CC + j] = acc;
}

__global__ void writeback_kernel(float* __restrict__ xr, float* __restrict__ xh) {
    int idx = blockIdx.x * blockDim.x + threadIdx.x;
    if (idx >= BS * 2 * CC) return;
    int c = idx % (2 * CC); int b = idx / (2 * CC);
    float v = g_ctx2[idx];
    bf16 hb, lb; split_bf(v, hb, lb);
    if (c < CC) {
        size_t o = (size_t)b * NN * CC + c;
        xr[o] = v; g_xrh[o] = hb; g_xrl[o] = lb;
    } else {
        size_t o = (size_t)b * NN * CC + (c - CC);
        xh[o] = v; g_xhh[o] = hb; g_xhl[o] = lb;
    }
}

// ---------------- launch ----------------
#define SYM(p, s) cudaGetSymbolAddress((void**)&p, s)

extern "C" void kernel_launch(void* const* d_in, const int* in_sizes, int n_in,
                              void* d_out, int out_size) {
    const float* spans  = (const float*)d_in[0];
    const float* svo    = (const float*)d_in[1];
    const float* pooled = (const float*)d_in[2];
    const int*   s2w    = (const int*)d_in[3];
    const int*   aug    = (const int*)d_in[4];
    const int*   punct  = (const int*)d_in[5];
    const float* w_rel  = (const float*)d_in[6];
    const float* w_root = (const float*)d_in[7];
    const float* b_rgcn = (const float*)d_in[8];
    const float* w_lin  = (const float*)d_in[9];
    const float* att_x  = (const float*)d_in[10];
    const float* att_e  = (const float*)d_in[11];
    const float* b_hgcn = (const float*)d_in[12];
    const float* ie_w1  = (const float*)d_in[13];
    const float* ie_b1  = (const float*)d_in[14];
    const float* ie_w2  = (const float*)d_in[15];
    const float* ie_b2  = (const float*)d_in[16];
    float* out = (float*)d_out;

    cudaFuncSetAttribute(gemm_kernel, cudaFuncAttributeMaxDynamicSharedMemorySize,
                         NSTG * STG_BYTES);

    float *p_ohp, *p_agg, *p_xr, *p_xh, *p_ctx, *p_h1, *p_ctx2;
    SYM(p_ohp, g_ohp); SYM(p_agg, g_agg);
    SYM(p_xr, g_xr); SYM(p_xh, g_xh);
    SYM(p_ctx, g_ctx); SYM(p_h1, g_h1); SYM(p_ctx2, g_ctx2);

    bf16 *x0h,*x0l,*wlh,*wll,*wcth,*wctl;
    bf16 *amnh,*amnl,*anmh,*anml,*th,*tl,*msgh,*msgl,*xch,*xcl,*Anh,*Anl;
    bf16 *xrh,*xrl,*xhh,*xhl;
    SYM(x0h, g_x0h); SYM(x0l, g_x0l);
    SYM(wlh, g_wlh); SYM(wll, g_wll);
    SYM(wcth, g_wcth); SYM(wctl, g_wctl);
    SYM(amnh, g_amnh); SYM(amnl, g_amnl);
    SYM(anmh, g_anmh); SYM(anml, g_anml);
    SYM(th, g_th); SYM(tl, g_tl);
    SYM(msgh, g_msgh); SYM(msgl, g_msgl);
    SYM(xch, g_xch); SYM(xcl, g_xcl);
    SYM(Anh, g_Anh); SYM(Anl, g_Anl);
    SYM(xrh, g_xrh); SYM(xrl, g_xrl); SYM(xhh, g_xhh); SYM(xhl, g_xhl);

    // ---- layer-invariant prep ----
    {
        size_t n;
        n = (size_t)BS*NN*CC;
        split_kernel<<<(int)((n+255)/256), 256>>>(spans, x0h, x0l, n);
        n = (size_t)LL*CC*HH*CC;
        split_kernel<<<(int)((n+255)/256), 256>>>(w_lin, wlh, wll, n);
        n = (size_t)LL*CC*3*CC;
        build_wcat_kernel<<<(int)((n+255)/256), 256>>>(w_rel, w_root);
    }
    prep_deg_kernel<<<(BS * NN + BS * MM + 127) / 128, 128>>>(s2w);
    prep_anorm_kernel<<<(2 * BS * NN + 127) / 128, 128>>>(aug, punct);

    const bf16 *Axh_h = x0h, *Axh_l = x0l;   // x_h planes
    const bf16 *Axr_h = x0h, *Axr_l = x0l;   // x_r planes

    for (int l = 0; l < LL; l++) {
        float* xr_out = (l == LL - 1) ? out : p_xr;
        float* xh_out = (l == LL - 1) ? out + (size_t)BS * NN * CC : p_xh;
        const float* wlf = w_lin + (size_t)l * CC * HH * CC;
        const bf16* wlhp = wlh + (size_t)l * CC * HH * CC;
        const bf16* wllp = wll + (size_t)l * CC * HH * CC;

        // ---- HypergraphConv (att-vector folded) ----
        compute_v_kernel<<<(2 * HH * CC * 32 + 255) / 256, 256>>>(
            wlf, att_x + (size_t)l * HH * CC, att_e + (size_t)l * HH * CC);
        ae_kernel<<<BS * MM, 128>>>(pooled, svo);
        alpha_kernel<<<BS * NN, 128>>>(Axh_h, Axh_l, s2w);
        // t[b,h] = alpha_mn[b,h] @ x_h[b]   [65,256]x[256,512], batch (b,h)
        gemm(amnh, amnl, Axh_h, Axh_l, nullptr, th, tl,
             MM, CC, NN, NN, CC, CC, BS*HH, HH,
             (long long)HH*MM*NN, (long long)MM*NN,
             (long long)NN*CC, 0,
             (long long)HH*MM*CC, (long long)MM*CC);
        // msg[b,h] = t[b,h] @ Wl[:, h-block]   [65,512]x[512,512], batch (b,h)
        gemm(th, tl, wlhp, wllp, nullptr, msgh, msgl,
             MM, CC, CC, CC, HH*CC, CC, BS*HH, HH,
             (long long)HH*MM*CC, (long long)MM*CC,
             0, (long long)CC,
             (long long)HH*MM*CC, (long long)MM*CC);
        // ohp = (alpha_nm*invB) @ msg   [256,65]x[65,512], batch (b,h)
        gemm(anmh, anml, msgh, msgl, p_ohp, nullptr, nullptr,
             NN, CC, MM, ALD, CC, CC, BS*HH, HH,
             (long long)HH*NN*ALD, (long long)NN*ALD,
             (long long)HH*MM*CC, (long long)MM*CC,
             (long long)HH*NN*CC, (long long)NN*CC);
        finalize_h_kernel<<<BS*NN, CC>>>(xh_out, b_hgcn + (size_t)l*CC);

        // ---- RGCN ----
        // xcat = x_r @ [wrel0|wrel1|wroot]   [8192,512]x[512,1536] -> planes
        gemm(Axr_h, Axr_l, wcth + (size_t)l*CC*3*CC, wctl + (size_t)l*CC*3*CC,
             nullptr, xch, xcl,
             BS*NN, 3*CC, CC, CC, 3*CC, 3*CC, 1, 1, 0,0,0,0,0,0);
        // agg[r][b] = Anorm[r][b] @ xw[r][b]   [256,256]x[256,512], batch 64
        // B = xcat slice: row i, col c at (b*NN+i)*3CC + r*CC + c
        gemm(Anh, Anl, xch, xcl, p_agg, nullptr, nullptr,
             NN, CC, NN, NN, 3*CC, CC, 2*BS, BS,
             (long long)BS*NN*NN, (long long)NN*NN,
             (long long)CC, (long long)NN*3*CC,
             (long long)BS*NN*CC, (long long)NN*CC);
        combine_rgcn_kernel<<<BS*NN, CC>>>(xr_out, b_rgcn + (size_t)l*CC);

        // ---- info exchange (row 0) ----
        build_ctx_kernel<<<(BS*2*CC + 255)/256, 256>>>(xr_out, xh_out);
        ie_gemm_kernel<<<dim3(2*CC/128, BS), 128>>>(
            p_ctx, ie_w1 + (size_t)l*2*CC*2*CC, ie_b1 + (size_t)l*2*CC, p_h1, 1);
        ie_gemm_kernel<<<dim3(2*CC/128, BS), 128>>>(
            p_h1, ie_w2 + (size_t)l*2*CC*2*CC, ie_b2 + (size_t)l*2*CC, p_ctx2, 0);
        writeback_kernel<<<(BS*2*CC + 255)/256, 256>>>(xr_out, xh_out);

        Axh_h = xhh; Axh_l = xhl;
        Axr_h = xrh; Axr_l = xrl;
    }
    (void)in_sizes; (void)n_in; (void)out_size;
}

// round 15
// speedup vs baseline: 1.1258x; 1.0705x over previous
#include <cuda_runtime.h>
#include <cuda_bf16.h>
#include <math.h>
#include <stdint.h>

#define BS 32
#define NN 256
#define EE 64
#define CC 512
#define HH 4
#define LL 2
#define MM 65
#define ALD 80   // padded lda for alpha_nm (160B rows, 16B aligned)

typedef __nv_bfloat16 bf16;

// ---------------- fp32 scratch ----------------
__device__ float g_ohp[(size_t)BS*HH*NN*CC];
__device__ float g_agg[(size_t)2*BS*NN*CC];
__device__ float g_xroot[(size_t)BS*NN*CC];
__device__ float g_xr[(size_t)BS*NN*CC];
__device__ float g_xh[(size_t)BS*NN*CC];
__device__ float g_ae[BS*MM*HH];
__device__ float g_vx[HH*CC];
__device__ float g_ve[HH*CC];
__device__ float g_invD[BS*NN];
__device__ float g_invB[BS*MM];
__device__ float g_ctx[BS*2*CC];
__device__ float g_h1[BS*2*CC];
__device__ float g_ctx2[BS*2*CC];

// ---------------- bf16 hi/lo planes ----------------
__device__ bf16 g_x0h[(size_t)BS*NN*CC],      g_x0l[(size_t)BS*NN*CC];
__device__ bf16 g_wlh[(size_t)LL*CC*HH*CC],   g_wll[(size_t)LL*CC*HH*CC];
__device__ bf16 g_wrh[(size_t)LL*2*CC*CC],    g_wrl[(size_t)LL*2*CC*CC];
__device__ bf16 g_wth[(size_t)LL*CC*CC],      g_wtl[(size_t)LL*CC*CC];
__device__ bf16 g_amnh[(size_t)BS*HH*MM*NN],  g_amnl[(size_t)BS*HH*MM*NN];
__device__ bf16 g_anmh[(size_t)BS*HH*NN*ALD], g_anml[(size_t)BS*HH*NN*ALD];
__device__ bf16 g_th[(size_t)HH*BS*MM*CC],    g_tl[(size_t)HH*BS*MM*CC];   // [h][b][m][c]
__device__ bf16 g_msgh[(size_t)HH*BS*MM*CC],  g_msgl[(size_t)HH*BS*MM*CC]; // [h][b][m][c]
__device__ bf16 g_xwh[(size_t)2*BS*NN*CC],    g_xwl[(size_t)2*BS*NN*CC];
__device__ bf16 g_Anh[(size_t)2*BS*NN*NN],    g_Anl[(size_t)2*BS*NN*NN];
__device__ bf16 g_xrh[(size_t)BS*NN*CC],      g_xrl[(size_t)BS*NN*CC];
__device__ bf16 g_xhh[(size_t)BS*NN*CC],      g_xhl[(size_t)BS*NN*CC];

// ---------------- helpers ----------------
__device__ __forceinline__ void split_bf(float x, bf16& h, bf16& l) {
    h = __float2bfloat16(x);
    l = __float2bfloat16(x - __bfloat162float(h));
}
__device__ __forceinline__ uint32_t pack_split_hi(float a, float b, uint32_t& lo_out) {
    bf16 h0, l0, h1, l1;
    split_bf(a, h0, l0); split_bf(b, h1, l1);
    __nv_bfloat162 hp; hp.x = h0; hp.y = h1;
    __nv_bfloat162 lp; lp.x = l0; lp.y = l1;
    uint32_t hv, lv;
    __builtin_memcpy(&hv, &hp, 4); __builtin_memcpy(&lv, &lp, 4);
    lo_out = lv; return hv;
}
__device__ __forceinline__ void mma_bf16(float* c, const uint32_t* a, const uint32_t* b) {
    asm volatile(
        "mma.sync.aligned.m16n8k16.row.col.f32.bf16.bf16.f32 "
        "{%0,%1,%2,%3}, {%4,%5,%6,%7}, {%8,%9}, {%0,%1,%2,%3};\n"
        : "+f"(c[0]), "+f"(c[1]), "+f"(c[2]), "+f"(c[3])
        : "r"(a[0]), "r"(a[1]), "r"(a[2]), "r"(a[3]), "r"(b[0]), "r"(b[1]));
}
__device__ __forceinline__ void cp16(uint32_t dst, const void* src, int sz) {
    asm volatile("cp.async.cg.shared.global [%0], [%1], 16, %2;\n"
                 :: "r"(dst), "l"(src), "r"(sz));
}
#define LDSM4(d0,d1,d2,d3,a) \
    asm volatile("ldmatrix.sync.aligned.m8n8.x4.shared.b16 {%0,%1,%2,%3}, [%4];" \
                 : "=r"(d0),"=r"(d1),"=r"(d2),"=r"(d3) : "r"(a))
#define LDSM4T(d0,d1,d2,d3,a) \
    asm volatile("ldmatrix.sync.aligned.m8n8.x4.trans.shared.b16 {%0,%1,%2,%3}, [%4];" \
                 : "=r"(d0),"=r"(d1),"=r"(d2),"=r"(d3) : "r"(a))

// ================= mma.sync split-bf16 GEMM (R8-proven config) =================
// C = (Ah+Al)@(Bh+Bl) via AhBh + AhBl + AlBh, fp32 accum.
// Tile 128x128x32, 256 threads, 8 warps (2x4), warp tile 64x32, mma m16n8k16.
// Double-buffered cp.async, ldmatrix fragment loads, XOR-swizzled smem.
#define STG_BYTES 32768   // per stage: Ah 8K | Al 8K | Bh 8K | Bl 8K

__global__ __launch_bounds__(256, 2)
void gemm_kernel(const bf16* __restrict__ Ah, const bf16* __restrict__ Al,
                 const bf16* __restrict__ Bh, const bf16* __restrict__ Bl,
                 float* __restrict__ Cf, bf16* __restrict__ Chp, bf16* __restrict__ Clp,
                 int Mr, int Nc, int K, int lda, int ldb, int ldc,
                 int zdiv,
                 long long sA1, long long sA2,
                 long long sB1, long long sB2,
                 long long sC1, long long sC2)
{
    extern __shared__ __align__(128) unsigned char smem_raw[];
    uint32_t smem = (uint32_t)__cvta_generic_to_shared(smem_raw);

    int z = blockIdx.z;
    int z1 = z / zdiv, z2 = z % zdiv;
    long long offA = z1 * sA1 + z2 * sA2;
    long long offB = z1 * sB1 + z2 * sB2;
    long long offC = z1 * sC1 + z2 * sC2;
    Ah += offA; Al += offA; Bh += offB; Bl += offB;

    const int tid = threadIdx.x;
    const int warp = tid >> 5, lane = tid & 31;
    const int wm = warp >> 2, wn = warp & 3;
    const int g = lane >> 2, tg = lane & 3;
    const int rowBase = blockIdx.y * 128;
    const int colBase = blockIdx.x * 128;

    int am[2], ac[2], adst[2];
    int bk[2], bc[2], bdst[2];
    #pragma unroll
    for (int i = 0; i < 2; i++) {
        int q = i * 256 + tid;
        am[i] = q >> 2; ac[i] = q & 3;
        adst[i] = am[i] * 64 + ((ac[i] ^ (am[i] & 3)) << 4);
        bk[i] = q >> 4; bc[i] = q & 15;
        bdst[i] = bk[i] * 256 + ((bc[i] ^ (bk[i] & 7)) << 4);
    }

    int mloc = wm * 64 + (lane & 15);
    int addrA0 = mloc * 64 + (((lane >> 4) ^ (mloc & 3)) << 4);
    int kB = lane & 15;
    int cB0 = wn * 4 + (lane >> 4);
    int addrB0 = kB * 256 + ((cB0 ^ (kB & 7)) << 4);

    float acc[4][4][4];
    #pragma unroll
    for (int i = 0; i < 4; i++)
        #pragma unroll
        for (int j = 0; j < 4; j++)
            #pragma unroll
            for (int r = 0; r < 4; r++) acc[i][j][r] = 0.f;

    const int S = (K + 31) / 32;

    auto copy_stage = [&](int s, int buf) {
        int k0 = s * 32;
        uint32_t base = smem + buf * STG_BYTES;
        #pragma unroll
        for (int i = 0; i < 2; i++) {
            int gr = rowBase + am[i];
            int kk = k0 + ac[i] * 8;
            int rem = (gr < Mr) ? (K - kk) * 2 : 0;
            int sz = rem < 0 ? 0 : (rem > 16 ? 16 : rem);
            int grc = (gr < Mr) ? gr : 0;
            int kkc = (sz > 0) ? kk : 0;
            size_t so = (size_t)grc * lda + kkc;
            cp16(base + adst[i],        Ah + so, sz);
            cp16(base + 8192 + adst[i], Al + so, sz);
        }
        #pragma unroll
        for (int i = 0; i < 2; i++) {
            int kk = k0 + bk[i];
            int gc = colBase + bc[i] * 8;
            int ok = (kk < K) && (gc < Nc);
            int kkc = ok ? kk : 0;
            int gcc = ok ? gc : 0;
            size_t so = (size_t)kkc * ldb + gcc;
            cp16(base + 16384 + bdst[i], Bh + so, ok ? 16 : 0);
            cp16(base + 24576 + bdst[i], Bl + so, ok ? 16 : 0);
        }
    };

    copy_stage(0, 0);
    asm volatile("cp.async.commit_group;\n");

    for (int s = 0; s < S; s++) {
        if (s + 1 < S) copy_stage(s + 1, (s + 1) & 1);
        asm volatile("cp.async.commit_group;\n");
        asm volatile("cp.async.wait_group 1;\n");
        __syncthreads();

        uint32_t aH = smem + (s & 1) * STG_BYTES;
        uint32_t aL = aH + 8192;
        uint32_t bH = aH + 16384;
        uint32_t bL = aH + 24576;

        #pragma unroll
        for (int ks = 0; ks < 2; ks++) {
            int axor = ks * 32;
            int bofs = ks * 4096;
            uint32_t Afh[4][4], Bfh[4][2];
            #pragma unroll
            for (int mt = 0; mt < 4; mt++)
                LDSM4(Afh[mt][0], Afh[mt][1], Afh[mt][2], Afh[mt][3],
                      aH + (uint32_t)(((addrA0 + mt * 1024) ^ axor)));
            #pragma unroll
            for (int u = 0; u < 2; u++) {
                uint32_t d0, d1, d2, d3;
                LDSM4T(d0, d1, d2, d3, bH + (uint32_t)(((addrB0 ^ (u * 32)) + bofs)));
                Bfh[2*u][0] = d0; Bfh[2*u][1] = d1;
                Bfh[2*u+1][0] = d2; Bfh[2*u+1][1] = d3;
            }
            #pragma unroll
            for (int mt = 0; mt < 4; mt++)
                #pragma unroll
                for (int nt = 0; nt < 4; nt++)
                    mma_bf16(acc[mt][nt], Afh[mt], Bfh[nt]);

            #pragma unroll
            for (int u = 0; u < 2; u++) {
                uint32_t d0, d1, d2, d3;
                LDSM4T(d0, d1, d2, d3, bL + (uint32_t)(((addrB0 ^ (u * 32)) + bofs)));
                uint32_t Bfl0[2] = {d0, d1}, Bfl1[2] = {d2, d3};
                #pragma unroll
                for (int mt = 0; mt < 4; mt++) {
                    mma_bf16(acc[mt][2*u],   Afh[mt], Bfl0);
                    mma_bf16(acc[mt][2*u+1], Afh[mt], Bfl1);
                }
            }
            #pragma unroll
            for (int mt = 0; mt < 4; mt++) {
                uint32_t Afl[4];
                LDSM4(Afl[0], Afl[1], Afl[2], Afl[3],
                      aL + (uint32_t)(((addrA0 + mt * 1024) ^ axor)));
                #pragma unroll
                for (int nt = 0; nt < 4; nt++)
                    mma_bf16(acc[mt][nt], Afl, Bfh[nt]);
            }
        }
        __syncthreads();
    }

    float* Cw = Cf ? (Cf + offC) : nullptr;
    bf16* Chw = Chp ? (Chp + offC) : nullptr;
    bf16* Clw = Clp ? (Clp + offC) : nullptr;
    #pragma unroll
    for (int mt = 0; mt < 4; mt++) {
        int r0 = rowBase + wm * 64 + mt * 16 + g;
        #pragma unroll
        for (int half = 0; half < 2; half++) {
            int r = r0 + half * 8;
            if (r >= Mr) continue;
            #pragma unroll
            for (int nt = 0; nt < 4; nt++) {
                int c = colBase + wn * 32 + nt * 8 + tg * 2;
                if (c >= Nc) continue;
                float v0 = acc[mt][nt][half * 2];
                float v1 = acc[mt][nt][half * 2 + 1];
                size_t o = (size_t)r * ldc + c;
                if (Cw) { Cw[o] = v0; Cw[o + 1] = v1; }
                if (Chw) {
                    uint32_t lv, hv = pack_split_hi(v0, v1, lv);
                    *(uint32_t*)(Chw + o) = hv;
                    *(uint32_t*)(Clw + o) = lv;
                }
            }
        }
    }
}

static void gemm(const bf16* Ah, const bf16* Al, const bf16* Bh, const bf16* Bl,
                 float* Cf, bf16* Chp, bf16* Clp,
                 int Mr, int Nc, int K, int lda, int ldb, int ldc,
                 int batch, int zdiv,
                 long long sA1, long long sA2, long long sB1, long long sB2,
                 long long sC1, long long sC2)
{
    dim3 grid((Nc + 127) / 128, (Mr + 127) / 128, batch);
    gemm_kernel<<<grid, 256, 2 * STG_BYTES>>>(Ah, Al, Bh, Bl, Cf, Chp, Clp,
        Mr, Nc, K, lda, ldb, ldc, zdiv, sA1, sA2, sB1, sB2, sC1, sC2);
}

// ---------------- prep kernels ----------------
__global__ void split_kernel(const float* __restrict__ in, bf16* __restrict__ hi,
                             bf16* __restrict__ lo, size_t n) {
    size_t i = (size_t)blockIdx.x * blockDim.x + threadIdx.x;
    if (i >= n) return;
    bf16 h, l; split_bf(in[i], h, l);
    hi[i] = h; lo[i] = l;
}

__global__ void prep_deg_kernel(const int* __restrict__ s2w) {
    int idx = blockIdx.x * blockDim.x + threadIdx.x;
    if (idx < BS * NN) {
        const int* row = s2w + (size_t)idx * EE;
        int s = 1;
        for (int e = 0; e < EE; e++) s += row[e];
        g_invD[idx] = 1.f / (float)s;
    } else if (idx < BS * NN + BS * MM) {
        int t = idx - BS * NN;
        int m = t % MM, b = t / MM;
        if (m == 0) g_invB[t] = 1.f / (float)NN;
        else {
            int s = 0;
            for (int n = 0; n < NN; n++) s += s2w[((size_t)(b * NN + n)) * EE + (m - 1)];
            g_invB[t] = (s > 0) ? 1.f / (float)s : 0.f;
        }
    }
}

__global__ void prep_anorm_kernel(const int* __restrict__ aug,
                                  const int* __restrict__ punct) {
    int t = blockIdx.x * blockDim.x + threadIdx.x;
    if (t >= 2 * BS * NN) return;
    int j = t % NN;
    int b = (t / NN) % BS;
    int r = t / (NN * BS);
    int cnt = 0;
    for (int i = 0; i < NN; i++) {
        int a = aug[((size_t)(b * NN + i)) * NN + j];
        int v = r ? a : (punct[((size_t)(b * NN + i)) * NN + j] * (1 - a));
        cnt += v;
    }
    float val = cnt ? 1.f / (float)cnt : 0.f;
    bf16 vh, vl; split_bf(val, vh, vl);
    size_t base = ((size_t)(r * BS + b) * NN + j) * NN;
    for (int i = 0; i < NN; i++) {
        int a = aug[((size_t)(b * NN + i)) * NN + j];
        int v = r ? a : (punct[((size_t)(b * NN + i)) * NN + j] * (1 - a));
        g_Anh[base + i] = v ? vh : (bf16)__float2bfloat16(0.f);
        g_Anl[base + i] = v ? vl : (bf16)__float2bfloat16(0.f);
    }
}

// ---------------- attention path (att-vector folding) ----------------
__global__ void compute_v_kernel(const float* __restrict__ wl,
                                 const float* __restrict__ attx,
                                 const float* __restrict__ atte) {
    int gw = (blockIdx.x * blockDim.x + threadIdx.x) >> 5;
    int lane = threadIdx.x & 31;
    if (gw >= 2 * HH * CC) return;
    int sel = gw / (HH * CC);
    int rem = gw % (HH * CC);
    int h = rem / CC, k = rem % CC;
    const float* att = (sel ? atte : attx) + h * CC;
    const float* row = wl + (size_t)k * (HH * CC) + h * CC;
    float acc = 0.f;
    for (int c = lane; c < CC; c += 32) acc += row[c] * att[c];
    #pragma unroll
    for (int o = 16; o; o >>= 1) acc += __shfl_xor_sync(0xffffffffu, acc, o);
    if (lane == 0) (sel ? g_ve : g_vx)[h * CC + k] = acc;
}

__global__ void ae_kernel(const float* __restrict__ pooled,
                          const float* __restrict__ svo) {
    int bm = blockIdx.x;
    int h = threadIdx.x >> 5, lane = threadIdx.x & 31;
    int b = bm / MM, m = bm % MM;
    const float* e = (m == 0) ? (pooled + (size_t)b * CC)
                              : (svo + ((size_t)(b * EE + (m - 1))) * CC);
    const float* v = g_ve + h * CC;
    float acc = 0.f;
    for (int c = lane; c < CC; c += 32) acc += e[c] * v[c];
    #pragma unroll
    for (int o = 16; o; o >>= 1) acc += __shfl_xor_sync(0xffffffffu, acc, o);
    if (lane == 0) g_ae[bm * HH + h] = acc;
}

// a_n inline + masked softmax; writes alpha_mn planes and invB-scaled alpha_nm planes
__global__ void alpha_kernel(const bf16* __restrict__ Xh, const bf16* __restrict__ Xl,
                             const int* __restrict__ s2w) {
    int bn = blockIdx.x;
    int b = bn >> 8, n = bn & 255;
    int h = threadIdx.x >> 5, lane = threadIdx.x & 31;
    const bf16* xh = Xh + (size_t)bn * CC;
    const bf16* xl = Xl + (size_t)bn * CC;
    const float* v = g_vx + h * CC;
    float anv = 0.f;
    for (int c = lane; c < CC; c += 32)
        anv += (__bfloat162float(xh[c]) + __bfloat162float(xl[c])) * v[c];
    #pragma unroll
    for (int o = 16; o; o >>= 1) anv += __shfl_xor_sync(0xffffffffu, anv, o);

    float vv3[3]; int ok[3];
    #pragma unroll
    for (int s = 0; s < 3; s++) {
        int m = lane + s * 32;
        float vv = -1e30f; int o = 0;
        if (m < MM) {
            o = (m == 0) || (s2w[(size_t)bn * EE + (m - 1)] != 0);
            if (o) {
                float x = anv + g_ae[(b * MM + m) * HH + h];
                vv = (x > 0.f) ? x : 0.2f * x;
            }
        }
        vv3[s] = vv; ok[s] = o;
    }
    float mx = fmaxf(vv3[0], fmaxf(vv3[1], vv3[2]));
    #pragma unroll
    for (int o = 16; o; o >>= 1) mx = fmaxf(mx, __shfl_xor_sync(0xffffffffu, mx, o));
    float e3[3]; float sum = 0.f;
    #pragma unroll
    for (int s = 0; s < 3; s++) { e3[s] = ok[s] ? expf(vv3[s] - mx) : 0.f; sum += e3[s]; }
    #pragma unroll
    for (int o = 16; o; o >>= 1) sum += __shfl_xor_sync(0xffffffffu, sum, o);
    float inv = 1.f / sum;
    size_t z = (size_t)(b * HH + h);
    #pragma unroll
    for (int s = 0; s < 3; s++) {
        int m = lane + s * 32;
        if (m < MM) {
            float a = e3[s] * inv;
            bf16 hb, lb;
            split_bf(a, hb, lb);
            size_t o1 = (z * MM + m) * NN + n;
            g_amnh[o1] = hb; g_amnl[o1] = lb;
            float as = a * g_invB[b * MM + m];
            split_bf(as, hb, lb);
            size_t o2 = (z * NN + n) * ALD + m;
            g_anmh[o2] = hb; g_anml[o2] = lb;
        }
    }
}

__global__ void finalize_h_kernel(float* __restrict__ out, const float* __restrict__ bias) {
    int bn = blockIdx.x; int c = threadIdx.x;
    int b = bn >> 8, n = bn & 255;
    float s = 0.f;
    #pragma unroll
    for (int h = 0; h < HH; h++)
        s += g_ohp[(((size_t)(b * HH + h)) * NN + n) * CC + c];
    float v = s * 0.25f * g_invD[bn] + bias[c];
    v = (v > 0.f) ? v : 0.f;
    size_t o = (size_t)bn * CC + c;
    out[o] = v;
    bf16 hb, lb; split_bf(v, hb, lb);
    g_xhh[o] = hb; g_xhl[o] = lb;
}

__global__ void combine_rgcn_kernel(float* __restrict__ out, const float* __restrict__ bias) {
    int bj = blockIdx.x; int c = threadIdx.x;
    size_t o = (size_t)bj * CC + c;
    float v = g_agg[o] + g_agg[(size_t)BS * NN * CC + o] + g_xroot[o] + bias[c];
    v = (v > 0.f) ? v : 0.f;
    out[o] = v;
    bf16 hb, lb; split_bf(v, hb, lb);
    g_xrh[o] = hb; g_xrl[o] = lb;
}

// ---------------- info exchange ----------------
__global__ void build_ctx_kernel(const float* __restrict__ xr, const float* __restrict__ xh) {
    int idx = blockIdx.x * blockDim.x + threadIdx.x;
    if (idx >= BS * 2 * CC) return;
    int c = idx % (2 * CC); int b = idx / (2 * CC);
    g_ctx[idx] = (c < CC) ? xr[(size_t)b * NN * CC + c]
                          : xh[(size_t)b * NN * CC + (c - CC)];
}

__global__ void ie_gemm_kernel(const float* __restrict__ in, const float* __restrict__ W,
                               const float* __restrict__ bias, float* __restrict__ out,
                               int relu) {
    __shared__ float s_in[2 * CC];
    int b = blockIdx.y;
    int j = blockIdx.x * 128 + threadIdx.x;
    for (int t = threadIdx.x; t < 2 * CC; t += 128) s_in[t] = in[b * 2 * CC + t];
    __syncthreads();
    float a0 = 0.f, a1 = 0.f, a2 = 0.f, a3 = 0.f;
    for (int k = 0; k < 2 * CC; k += 4) {
        a0 += s_in[k + 0] * W[(size_t)(k + 0) * (2 * CC) + j];
        a1 += s_in[k + 1] * W[(size_t)(k + 1) * (2 * CC) + j];
        a2 += s_in[k + 2] * W[(size_t)(k + 2) * (2 * CC) + j];
        a3 += s_in[k + 3] * W[(size_t)(k + 3) * (2 * CC) + j];
    }
    float acc = (a0 + a1) + (a2 + a3) + bias[j];
    if (relu) acc = (acc > 0.f) ? acc : 0.f;
    out[b * 2 * CC + j] = acc;
}

__global__ void writeback_kernel(float* __restrict__ xr, float* __restrict__ xh) {
    int idx = blockIdx.x * blockDim.x + threadIdx.x;
    if (idx >= BS * 2 * CC) return;
    int c = idx % (2 * CC); int b = idx / (2 * CC);
    float v = g_ctx2[idx];
    bf16 hb, lb; split_bf(v, hb, lb);
    if (c < CC) {
        size_t o = (size_t)b * NN * CC + c;
        xr[o] = v; g_xrh[o] = hb; g_xrl[o] = lb;
    } else {
        size_t o = (size_t)b * NN * CC + (c - CC);
        xh[o] = v; g_xhh[o] = hb; g_xhl[o] = lb;
    }
}

// ---------------- launch ----------------
#define SYM(p, s) cudaGetSymbolAddress((void**)&p, s)

extern "C" void kernel_launch(void* const* d_in, const int* in_sizes, int n_in,
                              void* d_out, int out_size) {
    const float* spans  = (const float*)d_in[0];
    const float* svo    = (const float*)d_in[1];
    const float* pooled = (const float*)d_in[2];
    const int*   s2w    = (const int*)d_in[3];
    const int*   aug    = (const int*)d_in[4];
    const int*   punct  = (const int*)d_in[5];
    const float* w_rel  = (const float*)d_in[6];
    const float* w_root = (const float*)d_in[7];
    const float* b_rgcn = (const float*)d_in[8];
    const float* w_lin  = (const float*)d_in[9];
    const float* att_x  = (const float*)d_in[10];
    const float* att_e  = (const float*)d_in[11];
    const float* b_hgcn = (const float*)d_in[12];
    const float* ie_w1  = (const float*)d_in[13];
    const float* ie_b1  = (const float*)d_in[14];
    const float* ie_w2  = (const float*)d_in[15];
    const float* ie_b2  = (const float*)d_in[16];
    float* out = (float*)d_out;

    cudaFuncSetAttribute(gemm_kernel, cudaFuncAttributeMaxDynamicSharedMemorySize,
                         2 * STG_BYTES);

    float *p_ohp, *p_agg, *p_xroot, *p_xr, *p_xh, *p_ctx, *p_h1, *p_ctx2;
    SYM(p_ohp, g_ohp); SYM(p_agg, g_agg); SYM(p_xroot, g_xroot);
    SYM(p_xr, g_xr); SYM(p_xh, g_xh);
    SYM(p_ctx, g_ctx); SYM(p_h1, g_h1); SYM(p_ctx2, g_ctx2);

    bf16 *x0h,*x0l,*wlh,*wll,*wrh,*wrl,*wth,*wtl;
    bf16 *amnh,*amnl,*anmh,*anml,*th,*tl,*msgh,*msgl,*xwh,*xwl,*Anh,*Anl;
    bf16 *xrh,*xrl,*xhh,*xhl;
    SYM(x0h, g_x0h); SYM(x0l, g_x0l);
    SYM(wlh, g_wlh); SYM(wll, g_wll); SYM(wrh, g_wrh); SYM(wrl, g_wrl);
    SYM(wth, g_wth); SYM(wtl, g_wtl);
    SYM(amnh, g_amnh); SYM(amnl, g_amnl);
    SYM(anmh, g_anmh); SYM(anml, g_anml);
    SYM(th, g_th); SYM(tl, g_tl);
    SYM(msgh, g_msgh); SYM(msgl, g_msgl);
    SYM(xwh, g_xwh); SYM(xwl, g_xwl); SYM(Anh, g_Anh); SYM(Anl, g_Anl);
    SYM(xrh, g_xrh); SYM(xrl, g_xrl); SYM(xhh, g_xhh); SYM(xhl, g_xhl);

    // ---- layer-invariant prep ----
    {
        size_t n;
        n = (size_t)BS*NN*CC;
        split_kernel<<<(int)((n+255)/256), 256>>>(spans, x0h, x0l, n);
        n = (size_t)LL*CC*HH*CC;
        split_kernel<<<(int)((n+255)/256), 256>>>(w_lin, wlh, wll, n);
        n = (size_t)LL*2*CC*CC;
        split_kernel<<<(int)((n+255)/256), 256>>>(w_rel, wrh, wrl, n);
        n = (size_t)LL*CC*CC;
        split_kernel<<<(int)((n+255)/256), 256>>>(w_root, wth, wtl, n);
    }
    prep_deg_kernel<<<(BS * NN + BS * MM + 127) / 128, 128>>>(s2w);
    prep_anorm_kernel<<<(2 * BS * NN + 127) / 128, 128>>>(aug, punct);

    const bf16 *Axh_h = x0h, *Axh_l = x0l;   // x_h planes
    const bf16 *Axr_h = x0h, *Axr_l = x0l;   // x_r planes

    for (int l = 0; l < LL; l++) {
        float* xr_out = (l == LL - 1) ? out : p_xr;
        float* xh_out = (l == LL - 1) ? out + (size_t)BS * NN * CC : p_xh;
        const float* wlf = w_lin + (size_t)l * CC * HH * CC;
        const bf16* wlhp = wlh + (size_t)l * CC * HH * CC;
        const bf16* wllp = wll + (size_t)l * CC * HH * CC;

        // ---- HypergraphConv (att-vector folded) ----
        compute_v_kernel<<<(2 * HH * CC * 32 + 255) / 256, 256>>>(
            wlf, att_x + (size_t)l * HH * CC, att_e + (size_t)l * HH * CC);
        ae_kernel<<<BS * MM, 128>>>(pooled, svo);
        alpha_kernel<<<BS * NN, 128>>>(Axh_h, Axh_l, s2w);
        // t = alpha_mn[b,h] @ x_h[b]   [65,256]x[256,512], batch z=(b,h),
        // C written in [h][b][m][c] layout via strides (z1=b, z2=h)
        gemm(amnh, amnl, Axh_h, Axh_l, nullptr, th, tl,
             MM, CC, NN, NN, CC, CC, BS*HH, HH,
             (long long)HH*MM*NN, (long long)MM*NN,
             (long long)NN*CC, 0,
             (long long)MM*CC, (long long)BS*MM*CC);
        // msg[h] = t[h] @ Wl[:, h-block]   [2080,512]x[512,512], batch 4 (h)
        gemm(th, tl, wlhp, wllp, nullptr, msgh, msgl,
             BS*MM, CC, CC, CC, HH*CC, CC, HH, 1,
             (long long)BS*MM*CC, 0,
             (long long)CC, 0,
             (long long)BS*MM*CC, 0);
        // ohp = (alpha_nm*invB) @ msg   [256,65]x[65,512], batch z=(b,h);
        // B = msg[h][b] via strides (z1=b: MM*CC, z2=h: BS*MM*CC)
        gemm(anmh, anml, msgh, msgl, p_ohp, nullptr, nullptr,
             NN, CC, MM, ALD, CC, CC, BS*HH, HH,
             (long long)HH*NN*ALD, (long long)NN*ALD,
             (long long)MM*CC, (long long)BS*MM*CC,
             (long long)HH*NN*CC, (long long)NN*CC);
        finalize_h_kernel<<<BS*NN, CC>>>(xh_out, b_hgcn + (size_t)l*CC);

        // ---- RGCN ----
        gemm(Axr_h, Axr_l, wrh + (size_t)l*2*CC*CC, wrl + (size_t)l*2*CC*CC,
             nullptr, xwh, xwl,
             BS*NN, CC, CC, CC, CC, CC, 2, 1,
             0, 0, (long long)CC*CC, 0, (long long)BS*NN*CC, 0);
        gemm(Axr_h, Axr_l, wth + (size_t)l*CC*CC, wtl + (size_t)l*CC*CC,
             p_xroot, nullptr, nullptr,
             BS*NN, CC, CC, CC, CC, CC, 1, 1, 0,0,0,0,0,0);
        gemm(Anh, Anl, xwh, xwl, p_agg, nullptr, nullptr,
             NN, CC, NN, NN, CC, CC, 2*BS, BS,
             (long long)BS*NN*NN, (long long)NN*NN,
             (long long)BS*NN*CC, (long long)NN*CC,
             (long long)BS*NN*CC, (long long)NN*CC);
        combine_rgcn_kernel<<<BS*NN, CC>>>(xr_out, b_rgcn + (size_t)l*CC);

        // ---- info exchange (row 0) ----
        build_ctx_kernel<<<(BS*2*CC + 255)/256, 256>>>(xr_out, xh_out);
        ie_gemm_kernel<<<dim3(2*CC/128, BS), 128>>>(
            p_ctx, ie_w1 + (size_t)l*2*CC*2*CC, ie_b1 + (size_t)l*2*CC, p_h1, 1);
        ie_gemm_kernel<<<dim3(2*CC/128, BS), 128>>>(
            p_h1, ie_w2 + (size_t)l*2*CC*2*CC, ie_b2 + (size_t)l*2*CC, p_ctx2, 0);
        writeback_kernel<<<(BS*2*CC + 255)/256, 256>>>(xr_out, xh_out);

        Axh_h = xhh; Axh_l = xhl;
        Axr_h = xrh; Axr_l = xrl;
    }
    (void)in_sizes; (void)n_in; (void)out_size;
}